// round 14
// baseline (speedup 1.0000x reference)
#include <cuda_runtime.h>
#include <cuda_bf16.h>
#include <cuda_fp16.h>
#include <math.h>
#include <stdint.h>

#define B_SZ 64
#define T_SZ 128
#define F_SZ 512
#define H_SZ 1024
#define P_SZ 1024
#define A_SZ 32
#define R_SZ 8192
#define G_SZ 4096
#define S_ST 3          /* cp.async pipeline stages */

typedef __nv_bfloat16 bf16;

// ---------------- scratch (static device globals) ---------------------------
__device__ float g_pre[(size_t)R_SZ * P_SZ];
__device__ float g_zx[(size_t)R_SZ * G_SZ];          // L0 input preacts [T][B][4H-perm]
__device__ float g_zpA[3][B_SZ * G_SZ];              // L0 split-K partials
__device__ float g_zpB[3][B_SZ * G_SZ];              // L1 split-K partials
__device__ float g_cst[2 * B_SZ * H_SZ];             // c state (both layers)
__device__ float g_hst[2 * B_SZ * H_SZ];             // h state fp32 (for output)

// recurrent A: fp16 split-2  [64][ h0h(1024) | h0l(1024) | h1h(1024) | h1l(1024) ]
__device__ __align__(256) __half g_Acat[B_SZ * 4096];
__device__ __align__(256) bf16 g_Ax  [(size_t)R_SZ * 3 * F_SZ];
__device__ __align__(256) bf16 g_Aln [(size_t)R_SZ * 3 * P_SZ];
__device__ __align__(256) bf16 g_Aseq1[(size_t)R_SZ * 3 * H_SZ];
__device__ __align__(256) bf16 g_Ahp [(size_t)R_SZ * 3 * P_SZ];

__device__ __align__(256) bf16 g_Bpre [(size_t)P_SZ * 3 * F_SZ];
__device__ __align__(256) bf16 g_Bwi0 [(size_t)G_SZ * 3 * P_SZ];
__device__ __align__(256) __half g_Bwh0h [(size_t)G_SZ * H_SZ];     // N-perm, fp16 hi
__device__ __align__(256) __half g_Bcat1h[(size_t)G_SZ * 2048];     // N-perm [Wi1h|Wh1h]
__device__ __align__(256) bf16 g_Bpost[(size_t)P_SZ * 3 * H_SZ];
__device__ __align__(256) bf16 g_Bout [(size_t)A_SZ * 3 * P_SZ];

// ---------------- helpers ---------------------------------------------------
__device__ __forceinline__ uint32_t smem_u32(const void* p) {
    uint32_t a;
    asm("{ .reg .u64 t; cvta.to.shared.u64 t, %1; cvt.u32.u64 %0, t; }" : "=r"(a) : "l"(p));
    return a;
}
#define SMEM_SWZ(o) ((o) ^ (((o) >> 3) & 0x70))
#define CP_ASYNC16(dst, src) \
    asm volatile("cp.async.cg.shared.global [%0], [%1], 16;" :: "r"(dst), "l"(src))
#define CP_COMMIT() asm volatile("cp.async.commit_group;" ::: "memory")
#define CP_WAIT2()  asm volatile("cp.async.wait_group 2;" ::: "memory")

__device__ __forceinline__ void ldmx4(uint32_t* r, uint32_t addr) {
    asm volatile("ldmatrix.sync.aligned.m8n8.x4.shared.b16 {%0,%1,%2,%3}, [%4];"
                 : "=r"(r[0]), "=r"(r[1]), "=r"(r[2]), "=r"(r[3]) : "r"(addr));
}
__device__ __forceinline__ void mma16816(float* c, const uint32_t* a, const uint32_t* b) {
    asm volatile("mma.sync.aligned.m16n8k16.row.col.f32.bf16.bf16.f32 "
                 "{%0,%1,%2,%3}, {%4,%5,%6,%7}, {%8,%9}, {%0,%1,%2,%3};"
                 : "+f"(c[0]), "+f"(c[1]), "+f"(c[2]), "+f"(c[3])
                 : "r"(a[0]), "r"(a[1]), "r"(a[2]), "r"(a[3]), "r"(b[0]), "r"(b[1]));
}
__device__ __forceinline__ void mma16816h(float* c, const uint32_t* a, const uint32_t* b) {
    asm volatile("mma.sync.aligned.m16n8k16.row.col.f32.f16.f16.f32 "
                 "{%0,%1,%2,%3}, {%4,%5,%6,%7}, {%8,%9}, {%0,%1,%2,%3};"
                 : "+f"(c[0]), "+f"(c[1]), "+f"(c[2]), "+f"(c[3])
                 : "r"(a[0]), "r"(a[1]), "r"(a[2]), "r"(a[3]), "r"(b[0]), "r"(b[1]));
}
__device__ __forceinline__ void split2(float v, bf16& hi, bf16& lo) {
    hi = __float2bfloat16_rn(v);
    lo = __float2bfloat16_rn(v - __bfloat162float(hi));
}
__device__ __forceinline__ void split2h(float v, __half& hi, __half& lo) {
    hi = __float2half_rn(v);
    lo = __float2half_rn(v - __half2float(hi));
}
__device__ __forceinline__ float sigmoidf_(float x) { return 1.f / (1.f + expf(-x)); }

// ---------------- big HMMA GEMM (feed-forward ops, bf16 split-3) -------------
// OUTMODE 0: fp32 row-major (+bias). 1: fp32 time-major [T][B][N] PERMUTED cols.
//         2: bf16-split [M, 3*Ntot] (+bias, relu).
template <int BM, int BN, int OUTMODE>
__global__ __launch_bounds__(256, 1) void gemm_mma(
    const bf16* __restrict__ Ap, const bf16* __restrict__ Bp,
    const float* __restrict__ bias, float* __restrict__ Cf,
    bf16* __restrict__ Cb, int Ntot, int K3)
{
    constexpr int WM = (BN == 32) ? 4 : 2;
    constexpr int WN = 8 / WM;
    constexpr int TM = BM / WM;
    constexpr int TN = BN / WN;
    constexpr int MT = TM / 16;
    constexpr int NT = TN / 8;
    constexpr int ABYTES = BM * 128;
    constexpr int BBYTES = BN * 128;

    extern __shared__ __align__(1024) char smem[];
    const uint32_t sA = smem_u32(smem);
    const uint32_t sB = sA + S_ST * ABYTES;

    const int tid = threadIdx.x;
    const int lane = tid & 31, wid = tid >> 5;
    const int wm = wid % WM, wn = wid / WM;
    const int bm = blockIdx.y * BM;
    const int bn = blockIdx.x * BN;
    const int NC = K3 / 64;

    const char* Ag = (const char*)(Ap + (size_t)bm * K3);
    const char* Bg = (const char*)(Bp + (size_t)bn * K3);
    const size_t rowB = (size_t)K3 * 2;

    float acc[MT][NT][4];
#pragma unroll
    for (int i = 0; i < MT; i++)
#pragma unroll
        for (int j = 0; j < NT; j++)
#pragma unroll
            for (int q = 0; q < 4; q++) acc[i][j][q] = 0.f;

    auto load_chunk = [&](int c, int stage) {
        const size_t coff = (size_t)c * 128;
        const uint32_t aT = sA + stage * ABYTES;
        const uint32_t bT = sB + stage * BBYTES;
#pragma unroll
        for (int i = 0; i < BM / 32; i++) {
            int seg = tid + i * 256, row = seg >> 3, so = (seg & 7) * 16;
            CP_ASYNC16(aT + SMEM_SWZ(row * 128 + so), Ag + (size_t)row * rowB + coff + so);
        }
#pragma unroll
        for (int i = 0; i < BN / 32; i++) {
            int seg = tid + i * 256, row = seg >> 3, so = (seg & 7) * 16;
            CP_ASYNC16(bT + SMEM_SWZ(row * 128 + so), Bg + (size_t)row * rowB + coff + so);
        }
    };

    load_chunk(0, 0); CP_COMMIT();
    load_chunk(1, 1); CP_COMMIT();

    const int a_row = wm * TM + (lane & 15);
    const int a_k16 = (lane >> 4) * 16;
    const int b_row = wn * TN + (lane & 7) + ((lane >> 4) << 3);
    const int b_k16 = ((lane >> 3) & 1) * 16;

    for (int c = 0; c < NC; c++) {
        int n = c + 2;
        if (n < NC) load_chunk(n, n % S_ST);
        CP_COMMIT();
        CP_WAIT2();
        __syncthreads();

        const uint32_t aT = sA + (c % S_ST) * ABYTES;
        const uint32_t bT = sB + (c % S_ST) * BBYTES;
#pragma unroll
        for (int ks = 0; ks < 4; ks++) {
            uint32_t af[MT][4], bfr[NT][2];
#pragma unroll
            for (int i = 0; i < MT; i++)
                ldmx4(af[i], aT + SMEM_SWZ((a_row + i * 16) * 128 + ks * 32 + a_k16));
#pragma unroll
            for (int jp = 0; jp < NT / 2; jp++) {
                uint32_t t4[4];
                ldmx4(t4, bT + SMEM_SWZ((b_row + jp * 16) * 128 + ks * 32 + b_k16));
                bfr[2 * jp][0] = t4[0]; bfr[2 * jp][1] = t4[1];
                bfr[2 * jp + 1][0] = t4[2]; bfr[2 * jp + 1][1] = t4[3];
            }
#pragma unroll
            for (int i = 0; i < MT; i++)
#pragma unroll
                for (int j = 0; j < NT; j++)
                    mma16816(acc[i][j], af[i], bfr[j]);
        }
        __syncthreads();
    }

#pragma unroll
    for (int i = 0; i < MT; i++) {
        const int r0 = bm + wm * TM + i * 16 + (lane >> 2);
        const int r1 = r0 + 8;
#pragma unroll
        for (int j = 0; j < NT; j++) {
            const int col = bn + wn * TN + j * 8 + (lane & 3) * 2;
            const float2 bv = *(const float2*)&bias[col];
            float v00 = acc[i][j][0] + bv.x, v01 = acc[i][j][1] + bv.y;
            float v10 = acc[i][j][2] + bv.x, v11 = acc[i][j][3] + bv.y;
            if (OUTMODE == 0) {
                *(float2*)&Cf[(size_t)r0 * Ntot + col] = make_float2(v00, v01);
                *(float2*)&Cf[(size_t)r1 * Ntot + col] = make_float2(v10, v11);
            } else if (OUTMODE == 1) {
                int b0i = r0 >> 7, t0 = r0 & 127, b1i = r1 >> 7, t1 = r1 & 127;
                int c0p = (col & 1023) * 4 + (col >> 10);
                int c1p = ((col + 1) & 1023) * 4 + ((col + 1) >> 10);
                float* q0 = Cf + ((size_t)t0 * B_SZ + b0i) * Ntot;
                float* q1 = Cf + ((size_t)t1 * B_SZ + b1i) * Ntot;
                q0[c0p] = v00; q0[c1p] = v01;
                q1[c0p] = v10; q1[c1p] = v11;
            } else {
                v00 = fmaxf(v00, 0.f); v01 = fmaxf(v01, 0.f);
                v10 = fmaxf(v10, 0.f); v11 = fmaxf(v11, 0.f);
                bf16 h0, l0, h1, l1;
                bf16* row0 = Cb + (size_t)r0 * 3 * Ntot;
                bf16* row1 = Cb + (size_t)r1 * 3 * Ntot;
                split2(v00, h0, l0); split2(v01, h1, l1);
                *(__nv_bfloat162*)&row0[col] = __nv_bfloat162(h0, h1);
                *(__nv_bfloat162*)&row0[Ntot + col] = __nv_bfloat162(h0, h1);
                *(__nv_bfloat162*)&row0[2 * Ntot + col] = __nv_bfloat162(l0, l1);
                split2(v10, h0, l0); split2(v11, h1, l1);
                *(__nv_bfloat162*)&row1[col] = __nv_bfloat162(h0, h1);
                *(__nv_bfloat162*)&row1[Ntot + col] = __nv_bfloat162(h0, h1);
                *(__nv_bfloat162*)&row1[2 * Ntot + col] = __nv_bfloat162(l0, l1);
            }
        }
    }
}

// ---------------- wavefront recurrent GEMM (fp16 split-2, shared B) ----------
// z = (Ah + Al) @ Bh.  Per chunk (64 bh cols): B loaded once, both A halves MMA'd.
// grid 144: CTAs 0..47  -> L0: 16 tiles(256) x 3 ks {6,5,5} chunks of 16
//           CTAs 48..143-> L1: 32 tiles(128) x 3 ks {11,11,10} chunks of 32
template <int NTILE>
__device__ __forceinline__ void wave_body(
    const char* Bg, size_t brs, float* zp, int tile, int cbeg, int nch)
{
    constexpr int TN = NTILE / 4;          // 64 or 32
    constexpr int NT = TN / 8;             // 8 or 4
    constexpr int STG_B = 49152;
    extern __shared__ __align__(1024) char smem[];
    const uint32_t s0 = smem_u32(smem);

    const int tid = threadIdx.x;
    const int lane = tid & 31, wid = tid >> 5;
    const int wm = wid & 1, wn = wid >> 1;
    const char* Ag = (const char*)g_Acat;   // [64][8192B]

    float acc[2][NT][4];
#pragma unroll
    for (int i = 0; i < 2; i++)
#pragma unroll
        for (int j = 0; j < NT; j++)
#pragma unroll
            for (int q = 0; q < 4; q++) acc[i][j][q] = 0.f;

    auto load_chunk = [&](int c, int st) {
        const int cc = cbeg + c;
        // uniform A-offset map: cc<16 -> h0 block, cc>=16 -> h1 block (L1 only)
        const size_t ahi = (cc < 16) ? (size_t)cc * 128 : 4096 + (size_t)(cc - 16) * 128;
        const uint32_t base = s0 + st * STG_B;
#pragma unroll
        for (int i = 0; i < 2; i++) {            // A hi: 64 rows x 8 segs
            int seg = tid + i * 256, row = seg >> 3, so = (seg & 7) * 16;
            CP_ASYNC16(base + SMEM_SWZ(row * 128 + so), Ag + (size_t)row * 8192 + ahi + so);
        }
#pragma unroll
        for (int i = 0; i < 2; i++) {            // A lo
            int seg = tid + i * 256, row = seg >> 3, so = (seg & 7) * 16;
            CP_ASYNC16(base + 8192 + SMEM_SWZ(row * 128 + so),
                       Ag + (size_t)row * 8192 + ahi + 2048 + so);
        }
#pragma unroll
        for (int i = 0; i < NTILE / 32; i++) {   // B: NTILE rows x 8 segs
            int seg = tid + i * 256, row = seg >> 3, so = (seg & 7) * 16;
            CP_ASYNC16(base + 16384 + SMEM_SWZ(row * 128 + so),
                       Bg + (size_t)row * brs + (size_t)cc * 128 + so);
        }
    };

    load_chunk(0, 0); CP_COMMIT();
    load_chunk(1, 1); CP_COMMIT();

    const int a_row = wm * 32 + (lane & 15);
    const int a_k16 = (lane >> 4) * 16;
    const int b_row = wn * TN + (lane & 7) + ((lane >> 4) << 3);
    const int b_k16 = ((lane >> 3) & 1) * 16;

    for (int c = 0; c < nch; c++) {
        int n = c + 2;
        if (n < nch) load_chunk(n, n % S_ST);
        CP_COMMIT();
        CP_WAIT2();
        __syncthreads();
        const uint32_t aHT = s0 + (c % S_ST) * STG_B;
        const uint32_t aLT = aHT + 8192;
        const uint32_t bT = aHT + 16384;
#pragma unroll
        for (int k4 = 0; k4 < 4; k4++) {
            uint32_t ah[2][4], al[2][4], bfr[NT][2];
#pragma unroll
            for (int i = 0; i < 2; i++) {
                ldmx4(ah[i], aHT + SMEM_SWZ((a_row + i * 16) * 128 + k4 * 32 + a_k16));
                ldmx4(al[i], aLT + SMEM_SWZ((a_row + i * 16) * 128 + k4 * 32 + a_k16));
            }
#pragma unroll
            for (int jp = 0; jp < NT / 2; jp++) {
                uint32_t t4[4];
                ldmx4(t4, bT + SMEM_SWZ((b_row + jp * 16) * 128 + k4 * 32 + b_k16));
                bfr[2 * jp][0] = t4[0]; bfr[2 * jp][1] = t4[1];
                bfr[2 * jp + 1][0] = t4[2]; bfr[2 * jp + 1][1] = t4[3];
            }
#pragma unroll
            for (int i = 0; i < 2; i++)
#pragma unroll
                for (int j = 0; j < NT; j++) {
                    mma16816h(acc[i][j], ah[i], bfr[j]);
                    mma16816h(acc[i][j], al[i], bfr[j]);
                }
        }
        __syncthreads();
    }

#pragma unroll
    for (int i = 0; i < 2; i++) {
        const int r0 = wm * 32 + i * 16 + (lane >> 2);
#pragma unroll
        for (int j = 0; j < NT; j++) {
            const int col = tile * NTILE + wn * TN + j * 8 + (lane & 3) * 2;
            *(float2*)&zp[(size_t)r0 * G_SZ + col] = make_float2(acc[i][j][0], acc[i][j][1]);
            *(float2*)&zp[(size_t)(r0 + 8) * G_SZ + col] = make_float2(acc[i][j][2], acc[i][j][3]);
        }
    }
}

__global__ __launch_bounds__(256, 1) void wave_gemm(int s)
{
    const int bx = blockIdx.x;
    if (bx < 48) {
        if (s >= 128) return;
        int tile = bx / 3, ks = bx % 3;
        int cbeg = (ks == 0) ? 0 : (ks == 1 ? 6 : 11);
        int nch  = (ks == 0) ? 6 : 5;
        wave_body<256>((const char*)g_Bwh0h + (size_t)(tile * 256) * 2048, 2048,
                       g_zpA[ks], tile, cbeg, nch);
    } else {
        if (s < 1) return;
        int bb = bx - 48;
        int tile = bb / 3, ks = bb % 3;
        int cbeg = ks * 11;
        int nch  = (ks == 2) ? 10 : 11;
        wave_body<128>((const char*)g_Bcat1h + (size_t)(tile * 128) * 4096, 4096,
                       g_zpB[ks], tile, cbeg, nch);
    }
}

// ---------------- wavefront gates --------------------------------------------
// grid 256: CTAs 0..127 -> L0 gates (t=s), CTAs 128..255 -> L1 gates (t=s-1).
__global__ __launch_bounds__(256) void wave_gates(
    const float* __restrict__ zx, const float* __restrict__ b1,
    bf16* __restrict__ Aseq1, int s)
{
    const int g = blockIdx.x, tid = threadIdx.x;
    if (g < 128) {
        if (s >= 128) return;
        const float* zx_t = zx + (size_t)s * B_SZ * G_SZ;
#pragma unroll
        for (int rep = 0; rep < 2; rep++) {
            int idx = g * 256 + tid + rep * 32768;      // 0..65535
            int b = idx >> 10, u = idx & 1023;
            size_t zo = (size_t)b * G_SZ + u * 4;
            float4 z = *(const float4*)&zx_t[zo];
#pragma unroll
            for (int p = 0; p < 3; p++) {
                float4 pz = *(const float4*)&g_zpA[p][zo];
                z.x += pz.x; z.y += pz.y; z.z += pz.z; z.w += pz.w;
            }
            int ci = b * H_SZ + u;
            float cn = sigmoidf_(z.y) * g_cst[ci] + sigmoidf_(z.x) * tanhf(z.z);
            float hn = sigmoidf_(z.w) * tanhf(cn);
            g_cst[ci] = cn;
            g_hst[ci] = hn;
            __half hh, hl; split2h(hn, hh, hl);
            __half* ra = g_Acat + (size_t)b * 4096;
            ra[u] = hh; ra[1024 + u] = hl;
        }
    } else {
        if (s < 1) return;
        const int t = s - 1;
#pragma unroll
        for (int rep = 0; rep < 2; rep++) {
            int idx = (g - 128) * 256 + tid + rep * 32768;
            int b = idx >> 10, u = idx & 1023;
            size_t zo = (size_t)b * G_SZ + u * 4;
            float4 z = make_float4(b1[u], b1[1024 + u], b1[2048 + u], b1[3072 + u]);
#pragma unroll
            for (int p = 0; p < 3; p++) {
                float4 pz = *(const float4*)&g_zpB[p][zo];
                z.x += pz.x; z.y += pz.y; z.z += pz.z; z.w += pz.w;
            }
            int ci = B_SZ * H_SZ + b * H_SZ + u;
            float cn = sigmoidf_(z.y) * g_cst[ci] + sigmoidf_(z.x) * tanhf(z.z);
            float hn = sigmoidf_(z.w) * tanhf(cn);
            g_cst[ci] = cn;
            g_hst[ci] = hn;
            __half hh, hl; split2h(hn, hh, hl);
            __half* ra = g_Acat + (size_t)b * 4096;
            ra[2048 + u] = hh; ra[3072 + u] = hl;
            bf16 bh, bl; split2(hn, bh, bl);
            bf16* rq = Aseq1 + ((size_t)b * T_SZ + t) * 3072;
            rq[u] = bh; rq[1024 + u] = bh; rq[2048 + u] = bl;
        }
    }
}

// ---------------- weight converts -------------------------------------------
// bf16 split-3 (FF): W[K,N] -> dest rows [hi|lo|hi], row-stride RS, K-off koff
template <int PERMN>
__global__ __launch_bounds__(256) void conv_w(const float* __restrict__ W,
    bf16* __restrict__ Bp, int K, int N, int RS, int koff)
{
    __shared__ float tile[32][33];
    const int n0 = blockIdx.x * 32, k0 = blockIdx.y * 32;
    const int tx = threadIdx.x & 31, ty = threadIdx.x >> 5;
    for (int i = ty; i < 32; i += 8)
        tile[i][tx] = W[(size_t)(k0 + i) * N + n0 + tx];
    __syncthreads();
    for (int i = ty; i < 32; i += 8) {
        int n = n0 + i, k = k0 + tx;
        int np = PERMN ? ((n & 1023) * 4 + (n >> 10)) : n;
        bf16 hi, lo; split2(tile[tx][i], hi, lo);
        bf16* row = Bp + (size_t)np * RS + koff;
        row[k] = hi; row[K + k] = lo; row[2 * K + k] = hi;
    }
}
// fp16 hi-only (recurrent weights), always N-permuted
__global__ __launch_bounds__(256) void conv_wh(const float* __restrict__ W,
    __half* __restrict__ Bp, int K, int N, int RS, int koff)
{
    __shared__ float tile[32][33];
    const int n0 = blockIdx.x * 32, k0 = blockIdx.y * 32;
    const int tx = threadIdx.x & 31, ty = threadIdx.x >> 5;
    for (int i = ty; i < 32; i += 8)
        tile[i][tx] = W[(size_t)(k0 + i) * N + n0 + tx];
    __syncthreads();
    for (int i = ty; i < 32; i += 8) {
        int n = n0 + i, k = k0 + tx;
        int np = (n & 1023) * 4 + (n >> 10);
        Bp[(size_t)np * RS + koff + k] = __float2half_rn(tile[tx][i]);
    }
}

// ---------------- activation convert: X[M,K] -> A'[M,3K] = [hi|hi|lo] -------
__global__ __launch_bounds__(256) void conv_x(const float* __restrict__ X,
                                              bf16* __restrict__ Ap, int K, int total)
{
    int i = blockIdx.x * 256 + threadIdx.x;
    if (i >= total) return;
    int r = i / K, k = i - r * K;
    bf16 hi, lo; split2(X[i], hi, lo);
    bf16* row = Ap + (size_t)r * 3 * K;
    row[k] = hi; row[K + k] = hi; row[2 * K + k] = lo;
}

// ---------------- LayerNorm + ReLU -> split bf16 ----------------------------
__global__ __launch_bounds__(256) void ln_relu(const float* __restrict__ buf,
    const float* __restrict__ gamma, const float* __restrict__ beta,
    bf16* __restrict__ Ap)
{
    __shared__ float rs[8], rs2[8];
    const int row = blockIdx.x;
    const float* p = buf + (size_t)row * P_SZ;
    const int tid = threadIdx.x;
    float4 v = *(const float4*)&p[tid * 4];
    float s = v.x + v.y + v.z + v.w;
    float s2 = v.x * v.x + v.y * v.y + v.z * v.z + v.w * v.w;
#pragma unroll
    for (int off = 16; off > 0; off >>= 1) {
        s += __shfl_xor_sync(0xFFFFFFFFu, s, off);
        s2 += __shfl_xor_sync(0xFFFFFFFFu, s2, off);
    }
    if ((tid & 31) == 0) { rs[tid >> 5] = s; rs2[tid >> 5] = s2; }
    __syncthreads();
    float tot = 0.f, tot2 = 0.f;
#pragma unroll
    for (int i = 0; i < 8; i++) { tot += rs[i]; tot2 += rs2[i]; }
    const float mu = tot * (1.f / 1024.f);
    const float r = rsqrtf(tot2 * (1.f / 1024.f) - mu * mu + 1e-6f);
    float4 g = *(const float4*)&gamma[tid * 4];
    float4 b = *(const float4*)&beta[tid * 4];
    float o[4] = { fmaxf((v.x - mu) * r * g.x + b.x, 0.f),
                   fmaxf((v.y - mu) * r * g.y + b.y, 0.f),
                   fmaxf((v.z - mu) * r * g.z + b.z, 0.f),
                   fmaxf((v.w - mu) * r * g.w + b.w, 0.f) };
    bf16* rp = Ap + (size_t)row * 3 * P_SZ;
#pragma unroll
    for (int q = 0; q < 4; q++) {
        int k = tid * 4 + q;
        bf16 hi, lo; split2(o[q], hi, lo);
        rp[k] = hi; rp[P_SZ + k] = hi; rp[2 * P_SZ + k] = lo;
    }
}

// ---------------- state init / export ---------------------------------------
__global__ __launch_bounds__(256) void init_state(
    const float* __restrict__ c0, const float* __restrict__ h0)
{
    int i = blockIdx.x * 256 + threadIdx.x;      // 0 .. 131071
    int l = i >> 16, r = i & 65535, b = r >> 10, u = r & 1023;
    g_cst[i] = c0[i];
    g_hst[i] = h0[i];
    __half hh, hl; split2h(h0[i], hh, hl);
    __half* ra = g_Acat + (size_t)b * 4096 + l * 2048;
    ra[u] = hh; ra[1024 + u] = hl;
}
__global__ __launch_bounds__(256) void copy_out(float* __restrict__ out)
{
    int i = blockIdx.x * 256 + threadIdx.x;      // 0 .. 131071
    out[i] = g_cst[i];
    out[131072 + i] = g_hst[i];
}

// ---------------- launch -----------------------------------------------------
extern "C" void kernel_launch(void* const* d_in, const int* in_sizes, int n_in,
                              void* d_out, int out_size)
{
    const float* x        = (const float*)d_in[0];
    const float* c0       = (const float*)d_in[1];
    const float* h0       = (const float*)d_in[2];
    const float* W_pre    = (const float*)d_in[3];
    const float* b_pre    = (const float*)d_in[4];
    const float* ln_scale = (const float*)d_in[5];
    const float* ln_bias  = (const float*)d_in[6];
    const float* Wi0      = (const float*)d_in[7];
    const float* Wh0      = (const float*)d_in[8];
    const float* b0       = (const float*)d_in[9];
    const float* Wi1      = (const float*)d_in[10];
    const float* Wh1      = (const float*)d_in[11];
    const float* b1       = (const float*)d_in[12];
    const float* W_post   = (const float*)d_in[13];
    const float* b_post   = (const float*)d_in[14];
    const float* W_out    = (const float*)d_in[15];
    const float* b_out    = (const float*)d_in[16];
    float* out = (float*)d_out;

    float *pre_p, *zx_p;
    bf16 *Ax, *Aln, *As1, *Ahp;
    bf16 *Bpre, *Bwi0, *Bpost, *Bout;
    __half *Bwh0h, *Bcat1h;
    cudaGetSymbolAddress((void**)&pre_p, g_pre);
    cudaGetSymbolAddress((void**)&zx_p, g_zx);
    cudaGetSymbolAddress((void**)&Ax, g_Ax);
    cudaGetSymbolAddress((void**)&Aln, g_Aln);
    cudaGetSymbolAddress((void**)&As1, g_Aseq1);
    cudaGetSymbolAddress((void**)&Ahp, g_Ahp);
    cudaGetSymbolAddress((void**)&Bpre, g_Bpre);
    cudaGetSymbolAddress((void**)&Bwi0, g_Bwi0);
    cudaGetSymbolAddress((void**)&Bwh0h, g_Bwh0h);
    cudaGetSymbolAddress((void**)&Bcat1h, g_Bcat1h);
    cudaGetSymbolAddress((void**)&Bpost, g_Bpost);
    cudaGetSymbolAddress((void**)&Bout, g_Bout);

    const int SMEM_128_128 = S_ST * (128 + 128) * 128;   // 98304
    const int SMEM_128_32  = S_ST * (128 + 32) * 128;    // 61440
    const int SMEM_WV      = S_ST * 49152;               // 147456
    cudaFuncSetAttribute(gemm_mma<128, 128, 0>, cudaFuncAttributeMaxDynamicSharedMemorySize, SMEM_128_128);
    cudaFuncSetAttribute(gemm_mma<128, 128, 1>, cudaFuncAttributeMaxDynamicSharedMemorySize, SMEM_128_128);
    cudaFuncSetAttribute(gemm_mma<128, 128, 2>, cudaFuncAttributeMaxDynamicSharedMemorySize, SMEM_128_128);
    cudaFuncSetAttribute(gemm_mma<128, 32, 0>,  cudaFuncAttributeMaxDynamicSharedMemorySize, SMEM_128_32);
    cudaFuncSetAttribute(wave_gemm,             cudaFuncAttributeMaxDynamicSharedMemorySize, SMEM_WV);

    // weight + input conversion
    conv_w<0><<<dim3(P_SZ / 32, F_SZ / 32), 256>>>(W_pre, Bpre, F_SZ, P_SZ, 3 * F_SZ, 0);
    conv_w<0><<<dim3(G_SZ / 32, P_SZ / 32), 256>>>(Wi0, Bwi0, P_SZ, G_SZ, 3 * P_SZ, 0);
    conv_wh<<<dim3(G_SZ / 32, H_SZ / 32), 256>>>(Wh0, Bwh0h, H_SZ, G_SZ, 1024, 0);
    conv_wh<<<dim3(G_SZ / 32, H_SZ / 32), 256>>>(Wi1, Bcat1h, H_SZ, G_SZ, 2048, 0);
    conv_wh<<<dim3(G_SZ / 32, H_SZ / 32), 256>>>(Wh1, Bcat1h, H_SZ, G_SZ, 2048, 1024);
    conv_w<0><<<dim3(P_SZ / 32, H_SZ / 32), 256>>>(W_post, Bpost, H_SZ, P_SZ, 3 * H_SZ, 0);
    conv_w<0><<<dim3(A_SZ / 32, P_SZ / 32), 256>>>(W_out, Bout, P_SZ, A_SZ, 3 * P_SZ, 0);
    conv_x<<<(R_SZ * F_SZ + 255) / 256, 256>>>(x, Ax, F_SZ, R_SZ * F_SZ);

    // pre dense -> fp32, then LN+relu -> split bf16
    gemm_mma<128, 128, 0><<<dim3(P_SZ / 128, R_SZ / 128), 256, SMEM_128_128>>>(
        Ax, Bpre, b_pre, pre_p, nullptr, P_SZ, 3 * F_SZ);
    ln_relu<<<R_SZ, 256>>>(pre_p, ln_scale, ln_bias, Aln);

    // layer-0 input gates for all timesteps (time-major, permuted cols)
    gemm_mma<128, 128, 1><<<dim3(G_SZ / 128, R_SZ / 128), 256, SMEM_128_128>>>(
        Aln, Bwi0, b0, zx_p, nullptr, G_SZ, 3 * P_SZ);

    // wavefront recurrence: step s runs L0 t=s and L1 t=s-1
    init_state<<<512, 256>>>(c0, h0);
    for (int s = 0; s <= T_SZ; s++) {
        wave_gemm<<<144, 256, SMEM_WV>>>(s);
        wave_gates<<<256, 256>>>(zx_p, b1, As1, s);
    }
    copy_out<<<512, 256>>>(out);

    // post dense + relu -> split bf16, then logits
    gemm_mma<128, 128, 2><<<dim3(P_SZ / 128, R_SZ / 128), 256, SMEM_128_128>>>(
        As1, Bpost, b_post, nullptr, Ahp, P_SZ, 3 * H_SZ);
    gemm_mma<128, 32, 0><<<dim3(1, R_SZ / 128), 256, SMEM_128_32>>>(
        Ahp, Bout, b_out, out + 4 * B_SZ * H_SZ, nullptr, A_SZ, 3 * P_SZ);
}